// round 15
// baseline (speedup 1.0000x reference)
#include <cuda_runtime.h>
#include <cstdint>

// ---------------- configuration ----------------
#define HB_BITS   16
#define HB        (1u << HB_BITS)     // 65536 coarse bins (top 16 raw bits)
#define LOWB      16
#define LOWN      (1u << LOWB)        // 65536 fine bins (low 16 mono bits)
#define NPART     148                 // one coarse-hist block per SM
#define MAX_SLOTS 32
#define QL_BITS   14
#define QLN       (1u << QL_BITS)     // 16384-entry quant LUT (top 14 raw bits)

// ---------------- static scratch ----------------
__device__ __align__(16) unsigned g_part1[(size_t)NPART * (HB / 2)];   // 19.4 MB packed u16, overwritten each run
__device__ __align__(16) unsigned g_hist16[HB];                        // mono-indexed, overwritten by k_reduce
__device__ __align__(16) unsigned g_hist2[(size_t)MAX_SLOTS * LOWN];   // 8 MB, zeroed by k_blutz
__device__ __align__(16) unsigned char g_lut16[HB];                    // RAW coarse bin -> slot+1 (rebuilt each run)
__device__ __align__(16) unsigned char g_qlut[QLN];                    // RAW 14-bit bin -> base | amb<<4 (rebuilt)
__device__ int      g_tbin[32];       // mono coarse bins of targets
__device__ unsigned g_trr[32];
__device__ int      g_tslot[32];
__device__ int      g_nslots;
__device__ float    g_tval[32];
__device__ float    g_cutv[16];
__device__ float4   g_q[16];          // x=1/step (A), y=-mn/step (B), z=step (C), w=mn (D)

// order-preserving maps
__device__ __forceinline__ unsigned mono_bits(unsigned b) {
    return b ^ ((unsigned)(((int)b) >> 31) | 0x80000000u);
}
__device__ __forceinline__ unsigned mono_key(float f) { return mono_bits(__float_as_uint(f)); }
__device__ __forceinline__ float unmono_key(unsigned k) {
    unsigned b = (k & 0x80000000u) ? (k & 0x7FFFFFFFu) : ~k;
    return __uint_as_float(b);
}
// 16-bit bin permutations between raw-bit order and mono (value) order
__device__ __forceinline__ unsigned raw2mono16(unsigned r) { return (r & 0x8000u) ? (r ^ 0xFFFFu) : (r ^ 0x8000u); }
__device__ __forceinline__ unsigned mono2raw16(unsigned m) { return (m & 0x8000u) ? (m ^ 0x8000u) : (m ^ 0xFFFFu); }

// ---------------- pass 1: raw 16-bit coarse histogram, packed u16 counters ----------------
__device__ __forceinline__ void h1_acc(unsigned sbase, float4 a) {
    unsigned k0 = __float_as_uint(a.x) >> 16, k1 = __float_as_uint(a.y) >> 16;
    unsigned k2 = __float_as_uint(a.z) >> 16, k3 = __float_as_uint(a.w) >> 16;
    asm volatile("red.shared.add.u32 [%0], %1;" :: "r"(sbase + (k0 >> 1) * 4u), "r"(1u << ((k0 & 1u) << 4)));
    asm volatile("red.shared.add.u32 [%0], %1;" :: "r"(sbase + (k1 >> 1) * 4u), "r"(1u << ((k1 & 1u) << 4)));
    asm volatile("red.shared.add.u32 [%0], %1;" :: "r"(sbase + (k2 >> 1) * 4u), "r"(1u << ((k2 & 1u) << 4)));
    asm volatile("red.shared.add.u32 [%0], %1;" :: "r"(sbase + (k3 >> 1) * 4u), "r"(1u << ((k3 & 1u) << 4)));
}

__global__ void __launch_bounds__(1024) k_hist1(const float4* __restrict__ x, int n4) {
    extern __shared__ unsigned sh[];              // HB/2 = 32768 words (128 KB)
    for (int i = threadIdx.x; i < (int)(HB / 2); i += 1024) sh[i] = 0u;
    __syncthreads();
    unsigned sbase = (unsigned)__cvta_generic_to_shared(sh);
    int T = gridDim.x * blockDim.x;
    int g = blockIdx.x * blockDim.x + threadIdx.x;
    for (int i = g; i < n4; i += 4 * T) {
        float4 a0 = __ldcs(&x[i]);
        bool h1 = (i + T) < n4, h2 = (i + 2 * T) < n4, h3 = (i + 3 * T) < n4;
        float4 a1, a2, a3;
        if (h1) a1 = __ldcs(&x[i + T]);
        if (h2) a2 = __ldcs(&x[i + 2 * T]);
        if (h3) a3 = __ldcs(&x[i + 3 * T]);
        h1_acc(sbase, a0);
        if (h1) h1_acc(sbase, a1);
        if (h2) h1_acc(sbase, a2);
        if (h3) h1_acc(sbase, a3);
    }
    __syncthreads();
    unsigned* dst = g_part1 + (size_t)blockIdx.x * (HB / 2);
    for (int i = threadIdx.x; i < (int)(HB / 2); i += 1024) dst[i] = sh[i];   // packed
}

// ---------------- reduce packed partials -> mono-ordered g_hist16 ----------------
__global__ void __launch_bounds__(1024) k_reduce() {
    unsigned w = blockIdx.x * 1024u + threadIdx.x;     // packed word index (raw bins 2w, 2w+1)
    unsigned lo = 0, hi = 0;
#pragma unroll 8
    for (int k = 0; k < NPART; k++) {
        unsigned v = g_part1[(size_t)k * (HB / 2) + w];
        lo += v & 0xFFFFu;
        hi += v >> 16;
    }
    g_hist16[raw2mono16(2u * w)]      = lo;
    g_hist16[raw2mono16(2u * w + 1u)] = hi;
}

// ---------------- scan coarse histogram (mono order), locate target bins ----------------
__global__ void __launch_bounds__(1024) k_scan1(unsigned n) {
    __shared__ unsigned pre[1024];
    __shared__ unsigned wsum[32];
    __shared__ int      sbin[32];
    __shared__ unsigned srr[32];
    __shared__ int      sslot[32];

    int t = threadIdx.x, lane = t & 31, w = t >> 5;
    unsigned s = 0;
    for (int k = 0; k < 64; k++) s += g_hist16[t * 64 + k];  // group sum (64 mono bins/thread)

    unsigned inc = s;
#pragma unroll
    for (int o = 1; o < 32; o <<= 1) {
        unsigned u = __shfl_up_sync(0xFFFFFFFFu, inc, o);
        if (lane >= o) inc += u;
    }
    if (lane == 31) wsum[w] = inc;
    __syncthreads();
    if (t < 32) {
        unsigned v = wsum[t], ss = v;
#pragma unroll
        for (int o = 1; o < 32; o <<= 1) {
            unsigned u = __shfl_up_sync(0xFFFFFFFFu, ss, o);
            if (t >= o) ss += u;
        }
        wsum[t] = ss - v;
    }
    __syncthreads();
    pre[t] = inc + wsum[w];          // inclusive prefix of 1024 group sums
    __syncthreads();

    if (t < 32) {
        unsigned S = n >> 4;
        unsigned r;
        if (t == 0)       r = 0u;
        else if (t == 31) r = n - 1u;
        else {
            unsigned c = (unsigned)(t + 1) >> 1;
            r = c * S - ((t & 1) ? 1u : 0u);
        }
        int lo = 0, hi = 1023;
        while (lo < hi) { int mid = (lo + hi) >> 1; if (pre[mid] > r) hi = mid; else lo = mid + 1; }
        unsigned run = lo ? pre[lo - 1] : 0u;
        int bin = -1;
        for (int k = 0; k < 64; k++) {
            unsigned c = g_hist16[lo * 64 + k];
            if (r < run + c) { bin = lo * 64 + k; srr[t] = r - run; break; }
            run += c;
        }
        sbin[t] = bin;
    }
    __syncthreads();

    for (int i = t; i < (int)HB; i += 1024) g_lut16[i] = 0;  // zero slot LUT (raw-indexed)
    if (t == 0) {
        int ns = 0;
        for (int i = 0; i < 32; i++) {
            int sl = -1;
            for (int j = 0; j < i; j++) if (sbin[j] == sbin[i]) { sl = sslot[j]; break; }
            if (sl < 0) sl = ns++;
            sslot[i] = sl;
        }
        g_nslots = ns;
    }
    __syncthreads();
    if (t == 0)
        for (int i = 0; i < 32; i++)
            g_lut16[mono2raw16((unsigned)sbin[i])] = (unsigned char)(sslot[i] + 1);
    if (t < 32) { g_tbin[t] = sbin[t]; g_trr[t] = srr[t]; g_tslot[t] = sslot[t]; }
}

// ---------------- pass 2: fine histogram (low 16 mono bits) for cut bins ----------------
// low16(mono) = (b ^ (int(b)>>31)) & 0xFFFF  (sign flip only; 0x80000000 never touches low bits)
__device__ __forceinline__ void h2_acc(const unsigned char* lut, float4 a) {
    float vv[4] = { a.x, a.y, a.z, a.w };
#pragma unroll
    for (int j = 0; j < 4; j++) {
        unsigned b = __float_as_uint(vv[j]);
        unsigned sl = lut[b >> 16];
        unsigned low = (b ^ (unsigned)(((int)b) >> 31)) & 0xFFFFu;
        unsigned* ptr = g_hist2 + (size_t)((sl - 1u) & 31u) * LOWN + low;   // masked: always in-bounds
        asm volatile("{\n\t"
                     ".reg .pred p;\n\t"
                     "setp.ne.u32 p, %0, 0;\n\t"
                     "@p red.global.add.u32 [%1], %2;\n\t"
                     "}" :: "r"(sl), "l"(ptr), "r"(1u) : "memory");
    }
}

__global__ void __launch_bounds__(512) k_hist2(const float4* __restrict__ x, int n4) {
    extern __shared__ unsigned char lut[];   // 64 KB, raw-indexed
    {
        const uint4* src = (const uint4*)g_lut16;
        uint4* dst = (uint4*)lut;
        for (int i = threadIdx.x; i < (int)(HB / 16); i += 512) dst[i] = src[i];
    }
    __syncthreads();
    int T = gridDim.x * blockDim.x;
    int g = blockIdx.x * blockDim.x + threadIdx.x;
    for (int i = g; i < n4; i += 4 * T) {
        float4 a0 = __ldcs(&x[i]);
        bool h1 = (i + T) < n4, h2 = (i + 2 * T) < n4, h3 = (i + 3 * T) < n4;
        float4 a1, a2, a3;
        if (h1) a1 = __ldcs(&x[i + T]);
        if (h2) a2 = __ldcs(&x[i + 2 * T]);
        if (h3) a3 = __ldcs(&x[i + 3 * T]);
        h2_acc(lut, a0);
        if (h1) h2_acc(lut, a1);
        if (h2) h2_acc(lut, a2);
        if (h3) h2_acc(lut, a3);
    }
}

// ---------------- scan2: one block per target scans its full 64K-bin slot ----------------
__global__ void __launch_bounds__(1024) k_scan2() {
    int t = blockIdx.x;                    // target 0..31
    int slot = g_tslot[t];
    unsigned rr = g_trr[t];
    unsigned bin = (unsigned)g_tbin[t];
    int tid = threadIdx.x, lane = tid & 31, w = tid >> 5;
    const uint4* h = (const uint4*)(g_hist2 + (size_t)slot * LOWN);

    // pass 1: sum 64 bins (16 uint4) per thread
    unsigned sum = 0;
#pragma unroll
    for (int i = 0; i < 16; i++) {
        uint4 u = h[tid * 16 + i];
        sum += u.x + u.y + u.z + u.w;
    }
    // block inclusive scan of 1024 thread sums
    __shared__ unsigned ws[32];
    unsigned inc = sum;
#pragma unroll
    for (int o = 1; o < 32; o <<= 1) {
        unsigned u = __shfl_up_sync(0xFFFFFFFFu, inc, o);
        if (lane >= o) inc += u;
    }
    if (lane == 31) ws[w] = inc;
    __syncthreads();
    if (tid < 32) {
        unsigned v = ws[tid], ss = v;
#pragma unroll
        for (int o = 1; o < 32; o <<= 1) {
            unsigned u = __shfl_up_sync(0xFFFFFFFFu, ss, o);
            if (tid >= o) ss += u;
        }
        ws[tid] = ss - v;                   // exclusive warp offsets
    }
    __syncthreads();
    unsigned excl = ws[w] + (inc - sum);
    if (rr >= excl && rr < excl + sum) {    // exactly one winner thread
        unsigned run = excl, low = 0;
        bool found = false;
        for (int i = 0; i < 16 && !found; i++) {
            uint4 u = h[tid * 16 + i];      // L1-hot re-read
            unsigned vv[4] = { u.x, u.y, u.z, u.w };
#pragma unroll
            for (int j = 0; j < 4; j++) {
                if (!found) {
                    if (rr < run + vv[j]) { low = (unsigned)(tid * 64 + i * 4 + j); found = true; }
                    else run += vv[j];
                }
            }
        }
        g_tval[t] = unmono_key((bin << LOWB) | low);
    }
}

// ---------------- blutz: per-chunk params + 14-bit quant LUT + zero hist2 ----------------
#define BLUTZ_LUT_BLOCKS (QLN / 1024)      // 16
#define BLUTZ_ZERO_BLOCKS 128
__global__ void __launch_bounds__(1024) k_blutz() {
    if (blockIdx.x < BLUTZ_LUT_BLOCKS) {
        __shared__ unsigned kc[16];
        int t = threadIdx.x;
        if (t < 16) {
            float mn = (t == 0)  ? g_tval[0]  : g_tval[2 * t];
            float mx = (t == 15) ? g_tval[31] : g_tval[2 * t + 1];
            float step = __fdiv_rn(__fsub_rn(mx, mn), 15.0f);
            float inv  = (step == 0.0f) ? 0.0f : __fdiv_rn(1.0f, step);
            float cut  = (t == 0) ? __int_as_float(0xFF800000) : mn;
            kc[t] = mono_key(cut);
            if (blockIdx.x == 0) {          // publish params for k_quant
                g_q[t]    = make_float4(inv, -mn * inv, step, mn);
                g_cutv[t] = cut;
            }
        }
        __syncthreads();
        unsigned r = blockIdx.x * 1024u + t;
        unsigned m0 = mono_bits(r << (32 - QL_BITS));
        unsigned m1 = mono_bits((r << (32 - QL_BITS)) | ((1u << (32 - QL_BITS)) - 1u));
        unsigned mlo = min(m0, m1), mhi = max(m0, m1);
        int base = 0, amb = 0;
#pragma unroll
        for (int j = 1; j < 16; j++) {
            unsigned k = kc[j];
            base += (k <= mlo);
            amb  += (k > mlo && k <= mhi);
        }
        g_qlut[r] = (unsigned char)(base | (amb << 4));
    } else {
        // zero the used fine-histogram slots for the next graph replay
        unsigned total4 = (unsigned)g_nslots * (LOWN / 4u);
        uint4* p = (uint4*)g_hist2;
        uint4 z = make_uint4(0u, 0u, 0u, 0u);
        unsigned id = (blockIdx.x - BLUTZ_LUT_BLOCKS) * 1024u + threadIdx.x;
        unsigned stride = BLUTZ_ZERO_BLOCKS * 1024u;
        for (; id < total4; id += stride) p[id] = z;
    }
}

// ---------------- final quantize pass ----------------
// Params via conflict-free replicated LDS.128: pq[c*8 + (lane&7)].
__device__ __forceinline__ float qone(float v, const unsigned char* lut,
                                      const float4* pq, const float* scut, int rep) {
    unsigned e = lut[__float_as_uint(v) >> (32 - QL_BITS)];
    int b = e & 15;
    int amb = e >> 4;
    int c = b + (int)((amb > 0) & (v >= scut[b + 1]));   // unconditional single fix-up
    if (amb > 1) {                                        // essentially never taken
#pragma unroll 1
        for (int t2 = 2; t2 <= amb; t2++) c += (v >= scut[b + t2]) ? 1 : 0;
    }
    float4 p = pq[c * 8 + rep];                           // {A, B, C, D}
    return fmaf(rintf(fmaf(v, p.x, p.y)), p.z, p.w);      // A==0 -> result D == mn == v
}

__global__ void __launch_bounds__(256) k_quant(const float4* __restrict__ x,
                                               float4* __restrict__ o, int n4) {
    __shared__ unsigned char lut[QLN];           // 16 KB
    __shared__ float4 pq[16 * 8];                // 2 KB replicated params
    __shared__ float  scut[20];
    {
        const uint4* src = (const uint4*)g_qlut;
        uint4* dst = (uint4*)lut;
        for (int i = threadIdx.x; i < (int)(QLN / 16); i += 256) dst[i] = src[i];
    }
    if (threadIdx.x < 128) pq[threadIdx.x] = g_q[threadIdx.x >> 3];
    if (threadIdx.x < 16)  scut[threadIdx.x] = g_cutv[threadIdx.x];
    if (threadIdx.x >= 16 && threadIdx.x < 20) scut[threadIdx.x] = __int_as_float(0x7F800000); // +inf pad
    __syncthreads();
    int rep = threadIdx.x & 7;
    int T = gridDim.x * blockDim.x;
    int g = blockIdx.x * blockDim.x + threadIdx.x;
    for (int i = g; i < n4; i += 4 * T) {        // warp-uniform bounds
        float4 a0 = __ldcs(&x[i]);
        bool h1 = (i + T) < n4, h2 = (i + 2 * T) < n4, h3 = (i + 3 * T) < n4;
        float4 a1, a2, a3;
        if (h1) a1 = __ldcs(&x[i + T]);
        if (h2) a2 = __ldcs(&x[i + 2 * T]);
        if (h3) a3 = __ldcs(&x[i + 3 * T]);
        float4 r0;
        r0.x = qone(a0.x, lut, pq, scut, rep);
        r0.y = qone(a0.y, lut, pq, scut, rep);
        r0.z = qone(a0.z, lut, pq, scut, rep);
        r0.w = qone(a0.w, lut, pq, scut, rep);
        __stcs(&o[i], r0);
        if (h1) {
            float4 r1;
            r1.x = qone(a1.x, lut, pq, scut, rep);
            r1.y = qone(a1.y, lut, pq, scut, rep);
            r1.z = qone(a1.z, lut, pq, scut, rep);
            r1.w = qone(a1.w, lut, pq, scut, rep);
            __stcs(&o[i + T], r1);
        }
        if (h2) {
            float4 r2;
            r2.x = qone(a2.x, lut, pq, scut, rep);
            r2.y = qone(a2.y, lut, pq, scut, rep);
            r2.z = qone(a2.z, lut, pq, scut, rep);
            r2.w = qone(a2.w, lut, pq, scut, rep);
            __stcs(&o[i + 2 * T], r2);
        }
        if (h3) {
            float4 r3;
            r3.x = qone(a3.x, lut, pq, scut, rep);
            r3.y = qone(a3.y, lut, pq, scut, rep);
            r3.z = qone(a3.z, lut, pq, scut, rep);
            r3.w = qone(a3.w, lut, pq, scut, rep);
            __stcs(&o[i + 3 * T], r3);
        }
    }
}

// ---------------- launcher ----------------
extern "C" void kernel_launch(void* const* d_in, const int* in_sizes, int n_in,
                              void* d_out, int out_size) {
    const float4* x = (const float4*)d_in[0];
    float4* out = (float4*)d_out;
    int n = in_sizes[0];
    int n4 = n / 4;

    cudaFuncSetAttribute(k_hist1, cudaFuncAttributeMaxDynamicSharedMemorySize, 131072);
    cudaFuncSetAttribute(k_hist2, cudaFuncAttributeMaxDynamicSharedMemorySize, 65536);

    k_hist1  <<< NPART, 1024, 131072 >>> (x, n4);   // raw 16-bit coarse histogram (packed u16)
    k_reduce <<< (HB / 2) / 1024, 1024 >>> ();      // sum packed partials -> mono-ordered g_hist16
    k_scan1  <<< 1, 1024 >>> ((unsigned)n);         // locate cut bins, slots, raw slot LUT
    k_hist2  <<< 888, 512, 65536 >>> (x, n4);       // fine histogram, predicated REDG, 4-wide MLP
    k_scan2  <<< 32, 1024 >>> ();                   // exact order statistics (full-slot block scan)
    k_blutz  <<< BLUTZ_LUT_BLOCKS + BLUTZ_ZERO_BLOCKS, 1024 >>> ();  // params + quant LUT + zero hist2
    k_quant  <<< 1184, 256 >>> (x, out, n4);        // quantize: byte-LUT + conflict-free LDS.128
}

// round 16
// speedup vs baseline: 1.0410x; 1.0410x over previous
#include <cuda_runtime.h>
#include <cstdint>

// ---------------- configuration ----------------
#define HB_BITS   16
#define HB        (1u << HB_BITS)     // 65536 coarse bins (top 16 raw bits)
#define LOWB      16
#define LOWN      (1u << LOWB)        // 65536 fine bins (low 16 mono bits)
#define NPART     148                 // one coarse-hist block per SM
#define MAX_SLOTS 32
#define QL_BITS   14
#define QLN       (1u << QL_BITS)     // 16384-entry quant LUT (top 14 raw bits)

// ---------------- static scratch ----------------
__device__ __align__(16) unsigned g_part1[(size_t)NPART * (HB / 2)];   // 19.4 MB packed u16, overwritten each run
__device__ __align__(16) unsigned g_hist16[HB];                        // mono-indexed, overwritten by k_reduce
__device__ __align__(16) unsigned g_hist2[(size_t)MAX_SLOTS * LOWN];   // 8 MB, zeroed by k_blutz
__device__ __align__(16) unsigned char g_lut16[HB];                    // RAW coarse bin -> slot+1 (rebuilt each run)
__device__ __align__(16) unsigned char g_qlut[QLN];                    // RAW 14-bit bin -> base | amb<<4 (rebuilt)
__device__ int      g_tbin[32];       // mono coarse bins of targets
__device__ unsigned g_trr[32];
__device__ int      g_tslot[32];
__device__ int      g_nslots;
__device__ float    g_tval[32];
__device__ float    g_cutv[16];
__device__ float4   g_q[16];          // x=1/step (A), y=-mn/step (B), z=step (C), w=mn (D)

// order-preserving maps
__device__ __forceinline__ unsigned mono_bits(unsigned b) {
    return b ^ ((unsigned)(((int)b) >> 31) | 0x80000000u);
}
__device__ __forceinline__ unsigned mono_key(float f) { return mono_bits(__float_as_uint(f)); }
__device__ __forceinline__ float unmono_key(unsigned k) {
    unsigned b = (k & 0x80000000u) ? (k & 0x7FFFFFFFu) : ~k;
    return __uint_as_float(b);
}
// 16-bit bin permutations between raw-bit order and mono (value) order
__device__ __forceinline__ unsigned raw2mono16(unsigned r) { return (r & 0x8000u) ? (r ^ 0xFFFFu) : (r ^ 0x8000u); }
__device__ __forceinline__ unsigned mono2raw16(unsigned m) { return (m & 0x8000u) ? (m ^ 0x8000u) : (m ^ 0xFFFFu); }

// ---------------- pass 1: raw 16-bit coarse histogram, packed u16 counters ----------------
__device__ __forceinline__ void h1_acc(unsigned sbase, float4 a) {
    unsigned k0 = __float_as_uint(a.x) >> 16, k1 = __float_as_uint(a.y) >> 16;
    unsigned k2 = __float_as_uint(a.z) >> 16, k3 = __float_as_uint(a.w) >> 16;
    asm volatile("red.shared.add.u32 [%0], %1;" :: "r"(sbase + (k0 >> 1) * 4u), "r"(1u << ((k0 & 1u) << 4)));
    asm volatile("red.shared.add.u32 [%0], %1;" :: "r"(sbase + (k1 >> 1) * 4u), "r"(1u << ((k1 & 1u) << 4)));
    asm volatile("red.shared.add.u32 [%0], %1;" :: "r"(sbase + (k2 >> 1) * 4u), "r"(1u << ((k2 & 1u) << 4)));
    asm volatile("red.shared.add.u32 [%0], %1;" :: "r"(sbase + (k3 >> 1) * 4u), "r"(1u << ((k3 & 1u) << 4)));
}

__global__ void __launch_bounds__(1024) k_hist1(const float4* __restrict__ x, int n4) {
    extern __shared__ unsigned sh[];              // HB/2 = 32768 words (128 KB)
    for (int i = threadIdx.x; i < (int)(HB / 2); i += 1024) sh[i] = 0u;
    __syncthreads();
    unsigned sbase = (unsigned)__cvta_generic_to_shared(sh);
    int T = gridDim.x * blockDim.x;
    int g = blockIdx.x * blockDim.x + threadIdx.x;
    for (int i = g; i < n4; i += 4 * T) {
        float4 a0 = __ldcs(&x[i]);
        bool h1 = (i + T) < n4, h2 = (i + 2 * T) < n4, h3 = (i + 3 * T) < n4;
        float4 a1, a2, a3;
        if (h1) a1 = __ldcs(&x[i + T]);
        if (h2) a2 = __ldcs(&x[i + 2 * T]);
        if (h3) a3 = __ldcs(&x[i + 3 * T]);
        h1_acc(sbase, a0);
        if (h1) h1_acc(sbase, a1);
        if (h2) h1_acc(sbase, a2);
        if (h3) h1_acc(sbase, a3);
    }
    __syncthreads();
    unsigned* dst = g_part1 + (size_t)blockIdx.x * (HB / 2);
    for (int i = threadIdx.x; i < (int)(HB / 2); i += 1024) __stcs(&dst[i], sh[i]);   // packed
}

// ---------------- reduce packed partials -> mono-ordered g_hist16 ----------------
__global__ void __launch_bounds__(1024) k_reduce() {
    unsigned w = blockIdx.x * 1024u + threadIdx.x;     // packed word index (raw bins 2w, 2w+1)
    unsigned lo = 0, hi = 0;
#pragma unroll 8
    for (int k = 0; k < NPART; k++) {
        unsigned v = g_part1[(size_t)k * (HB / 2) + w];
        lo += v & 0xFFFFu;
        hi += v >> 16;
    }
    g_hist16[raw2mono16(2u * w)]      = lo;
    g_hist16[raw2mono16(2u * w + 1u)] = hi;
}

// ---------------- scan coarse histogram (mono order), locate target bins ----------------
__global__ void __launch_bounds__(1024) k_scan1(unsigned n) {
    __shared__ unsigned pre[1024];
    __shared__ unsigned wsum[32];
    __shared__ int      sbin[32];
    __shared__ unsigned srr[32];
    __shared__ int      sslot[32];

    int t = threadIdx.x, lane = t & 31, w = t >> 5;
    unsigned s = 0;
    for (int k = 0; k < 64; k++) s += g_hist16[t * 64 + k];  // group sum (64 mono bins/thread)

    unsigned inc = s;
#pragma unroll
    for (int o = 1; o < 32; o <<= 1) {
        unsigned u = __shfl_up_sync(0xFFFFFFFFu, inc, o);
        if (lane >= o) inc += u;
    }
    if (lane == 31) wsum[w] = inc;
    __syncthreads();
    if (t < 32) {
        unsigned v = wsum[t], ss = v;
#pragma unroll
        for (int o = 1; o < 32; o <<= 1) {
            unsigned u = __shfl_up_sync(0xFFFFFFFFu, ss, o);
            if (t >= o) ss += u;
        }
        wsum[t] = ss - v;
    }
    __syncthreads();
    pre[t] = inc + wsum[w];          // inclusive prefix of 1024 group sums
    __syncthreads();

    if (t < 32) {
        unsigned S = n >> 4;
        unsigned r;
        if (t == 0)       r = 0u;
        else if (t == 31) r = n - 1u;
        else {
            unsigned c = (unsigned)(t + 1) >> 1;
            r = c * S - ((t & 1) ? 1u : 0u);
        }
        int lo = 0, hi = 1023;
        while (lo < hi) { int mid = (lo + hi) >> 1; if (pre[mid] > r) hi = mid; else lo = mid + 1; }
        unsigned run = lo ? pre[lo - 1] : 0u;
        int bin = -1;
        for (int k = 0; k < 64; k++) {
            unsigned c = g_hist16[lo * 64 + k];
            if (r < run + c) { bin = lo * 64 + k; srr[t] = r - run; break; }
            run += c;
        }
        sbin[t] = bin;
    }
    __syncthreads();

    for (int i = t; i < (int)HB; i += 1024) g_lut16[i] = 0;  // zero slot LUT (raw-indexed)
    if (t == 0) {
        int ns = 0;
        for (int i = 0; i < 32; i++) {
            int sl = -1;
            for (int j = 0; j < i; j++) if (sbin[j] == sbin[i]) { sl = sslot[j]; break; }
            if (sl < 0) sl = ns++;
            sslot[i] = sl;
        }
        g_nslots = ns;
    }
    __syncthreads();
    if (t == 0)
        for (int i = 0; i < 32; i++)
            g_lut16[mono2raw16((unsigned)sbin[i])] = (unsigned char)(sslot[i] + 1);
    if (t < 32) { g_tbin[t] = sbin[t]; g_trr[t] = srr[t]; g_tslot[t] = sslot[t]; }
}

// ---------------- pass 2: fine histogram (low 16 mono bits) for cut bins ----------------
// 32-bit offset math: off = slot<<16 | low16(mono);  low16(mono) = (b ^ (int(b)>>31)) & 0xFFFF
__device__ __forceinline__ void h2_acc(const unsigned char* lut, float4 a) {
    float vv[4] = { a.x, a.y, a.z, a.w };
#pragma unroll
    for (int j = 0; j < 4; j++) {
        unsigned b = __float_as_uint(vv[j]);
        unsigned sl = lut[b >> 16];
        unsigned low = (b ^ (unsigned)(((int)b) >> 31)) & 0xFFFFu;
        unsigned off = (((sl - 1u) & 31u) << 16) | low;        // masked: always in-bounds
        unsigned* ptr = g_hist2 + off;
        asm volatile("{\n\t"
                     ".reg .pred p;\n\t"
                     "setp.ne.u32 p, %0, 0;\n\t"
                     "@p red.global.add.u32 [%1], %2;\n\t"
                     "}" :: "r"(sl), "l"(ptr), "r"(1u) : "memory");
    }
}

__global__ void __launch_bounds__(512) k_hist2(const float4* __restrict__ x, int n4) {
    extern __shared__ unsigned char lut[];   // 64 KB, raw-indexed
    {
        const uint4* src = (const uint4*)g_lut16;
        uint4* dst = (uint4*)lut;
        for (int i = threadIdx.x; i < (int)(HB / 16); i += 512) dst[i] = src[i];
    }
    __syncthreads();
    int T = gridDim.x * blockDim.x;
    int g = blockIdx.x * blockDim.x + threadIdx.x;
    for (int i = g; i < n4; i += 4 * T) {
        float4 a0 = __ldcs(&x[i]);
        bool h1 = (i + T) < n4, h2 = (i + 2 * T) < n4, h3 = (i + 3 * T) < n4;
        float4 a1, a2, a3;
        if (h1) a1 = __ldcs(&x[i + T]);
        if (h2) a2 = __ldcs(&x[i + 2 * T]);
        if (h3) a3 = __ldcs(&x[i + 3 * T]);
        h2_acc(lut, a0);
        if (h1) h2_acc(lut, a1);
        if (h2) h2_acc(lut, a2);
        if (h3) h2_acc(lut, a3);
    }
}

// ---------------- scan2: one block per target scans its full 64K-bin slot ----------------
__global__ void __launch_bounds__(1024) k_scan2() {
    int t = blockIdx.x;                    // target 0..31
    int slot = g_tslot[t];
    unsigned rr = g_trr[t];
    unsigned bin = (unsigned)g_tbin[t];
    int tid = threadIdx.x, lane = tid & 31, w = tid >> 5;
    const uint4* h = (const uint4*)(g_hist2 + ((unsigned)slot << 16));

    // pass 1: sum 64 bins (16 uint4) per thread
    unsigned sum = 0;
#pragma unroll
    for (int i = 0; i < 16; i++) {
        uint4 u = h[tid * 16 + i];
        sum += u.x + u.y + u.z + u.w;
    }
    // block inclusive scan of 1024 thread sums
    __shared__ unsigned ws[32];
    unsigned inc = sum;
#pragma unroll
    for (int o = 1; o < 32; o <<= 1) {
        unsigned u = __shfl_up_sync(0xFFFFFFFFu, inc, o);
        if (lane >= o) inc += u;
    }
    if (lane == 31) ws[w] = inc;
    __syncthreads();
    if (tid < 32) {
        unsigned v = ws[tid], ss = v;
#pragma unroll
        for (int o = 1; o < 32; o <<= 1) {
            unsigned u = __shfl_up_sync(0xFFFFFFFFu, ss, o);
            if (tid >= o) ss += u;
        }
        ws[tid] = ss - v;                   // exclusive warp offsets
    }
    __syncthreads();
    unsigned excl = ws[w] + (inc - sum);
    if (rr >= excl && rr < excl + sum) {    // exactly one winner thread
        unsigned run = excl, low = 0;
        bool found = false;
        for (int i = 0; i < 16 && !found; i++) {
            uint4 u = h[tid * 16 + i];      // L1-hot re-read
            unsigned vv[4] = { u.x, u.y, u.z, u.w };
#pragma unroll
            for (int j = 0; j < 4; j++) {
                if (!found) {
                    if (rr < run + vv[j]) { low = (unsigned)(tid * 64 + i * 4 + j); found = true; }
                    else run += vv[j];
                }
            }
        }
        g_tval[t] = unmono_key((bin << LOWB) | low);
    }
}

// ---------------- blutz: per-chunk params + 14-bit quant LUT + zero hist2 ----------------
#define BLUTZ_LUT_BLOCKS (QLN / 1024)      // 16
#define BLUTZ_ZERO_BLOCKS 128
__global__ void __launch_bounds__(1024) k_blutz() {
    if (blockIdx.x < BLUTZ_LUT_BLOCKS) {
        __shared__ unsigned kc[16];
        int t = threadIdx.x;
        if (t < 16) {
            float mn = (t == 0)  ? g_tval[0]  : g_tval[2 * t];
            float mx = (t == 15) ? g_tval[31] : g_tval[2 * t + 1];
            float step = __fdiv_rn(__fsub_rn(mx, mn), 15.0f);
            float inv  = (step == 0.0f) ? 0.0f : __fdiv_rn(1.0f, step);
            float cut  = (t == 0) ? __int_as_float(0xFF800000) : mn;
            kc[t] = mono_key(cut);
            if (blockIdx.x == 0) {          // publish params for k_quant
                g_q[t]    = make_float4(inv, -mn * inv, step, mn);
                g_cutv[t] = cut;
            }
        }
        __syncthreads();
        unsigned r = blockIdx.x * 1024u + t;
        unsigned m0 = mono_bits(r << (32 - QL_BITS));
        unsigned m1 = mono_bits((r << (32 - QL_BITS)) | ((1u << (32 - QL_BITS)) - 1u));
        unsigned mlo = min(m0, m1), mhi = max(m0, m1);
        int base = 0, amb = 0;
#pragma unroll
        for (int j = 1; j < 16; j++) {
            unsigned k = kc[j];
            base += (k <= mlo);
            amb  += (k > mlo && k <= mhi);
        }
        g_qlut[r] = (unsigned char)(base | (amb << 4));
    } else {
        // zero the used fine-histogram slots for the next graph replay
        unsigned total4 = (unsigned)g_nslots * (LOWN / 4u);
        uint4* p = (uint4*)g_hist2;
        uint4 z = make_uint4(0u, 0u, 0u, 0u);
        unsigned id = (blockIdx.x - BLUTZ_LUT_BLOCKS) * 1024u + threadIdx.x;
        unsigned stride = BLUTZ_ZERO_BLOCKS * 1024u;
        for (; id < total4; id += stride) p[id] = z;
    }
}

// ---------------- final quantize pass (R14-proven 2-wide) ----------------
// Params via conflict-free replicated LDS.128: pq[c*8 + (lane&7)].
__device__ __forceinline__ float qone(float v, const unsigned char* lut,
                                      const float4* pq, const float* scut, int rep) {
    unsigned e = lut[__float_as_uint(v) >> (32 - QL_BITS)];
    int b = e & 15;
    int amb = e >> 4;
    int c = b + (int)((amb > 0) & (v >= scut[b + 1]));   // unconditional single fix-up
    if (amb > 1) {                                        // essentially never taken
#pragma unroll 1
        for (int t2 = 2; t2 <= amb; t2++) c += (v >= scut[b + t2]) ? 1 : 0;
    }
    float4 p = pq[c * 8 + rep];                           // {A, B, C, D}
    return fmaf(rintf(fmaf(v, p.x, p.y)), p.z, p.w);      // A==0 -> result D == mn == v
}

__global__ void __launch_bounds__(256) k_quant(const float4* __restrict__ x,
                                               float4* __restrict__ o, int n4) {
    __shared__ unsigned char lut[QLN];           // 16 KB
    __shared__ float4 pq[16 * 8];                // 2 KB replicated params
    __shared__ float  scut[20];
    {
        const uint4* src = (const uint4*)g_qlut;
        uint4* dst = (uint4*)lut;
        for (int i = threadIdx.x; i < (int)(QLN / 16); i += 256) dst[i] = src[i];
    }
    if (threadIdx.x < 128) pq[threadIdx.x] = g_q[threadIdx.x >> 3];
    if (threadIdx.x < 16)  scut[threadIdx.x] = g_cutv[threadIdx.x];
    if (threadIdx.x >= 16 && threadIdx.x < 20) scut[threadIdx.x] = __int_as_float(0x7F800000); // +inf pad
    __syncthreads();
    int rep = threadIdx.x & 7;
    int T = gridDim.x * blockDim.x;
    int g = blockIdx.x * blockDim.x + threadIdx.x;
    for (int i = g; i < n4; i += 2 * T) {        // warp-uniform bounds (n4, T multiples of 32)
        float4 a = __ldcs(&x[i]);
        bool hb = (i + T) < n4;
        float4 b;
        if (hb) b = __ldcs(&x[i + T]);
        float4 ra;
        ra.x = qone(a.x, lut, pq, scut, rep);
        ra.y = qone(a.y, lut, pq, scut, rep);
        ra.z = qone(a.z, lut, pq, scut, rep);
        ra.w = qone(a.w, lut, pq, scut, rep);
        __stcs(&o[i], ra);
        if (hb) {
            float4 rb;
            rb.x = qone(b.x, lut, pq, scut, rep);
            rb.y = qone(b.y, lut, pq, scut, rep);
            rb.z = qone(b.z, lut, pq, scut, rep);
            rb.w = qone(b.w, lut, pq, scut, rep);
            __stcs(&o[i + T], rb);
        }
    }
}

// ---------------- launcher ----------------
extern "C" void kernel_launch(void* const* d_in, const int* in_sizes, int n_in,
                              void* d_out, int out_size) {
    const float4* x = (const float4*)d_in[0];
    float4* out = (float4*)d_out;
    int n = in_sizes[0];
    int n4 = n / 4;

    cudaFuncSetAttribute(k_hist1, cudaFuncAttributeMaxDynamicSharedMemorySize, 131072);
    cudaFuncSetAttribute(k_hist2, cudaFuncAttributeMaxDynamicSharedMemorySize, 65536);

    k_hist1  <<< NPART, 1024, 131072 >>> (x, n4);   // raw 16-bit coarse histogram (packed u16)
    k_reduce <<< (HB / 2) / 1024, 1024 >>> ();      // sum packed partials -> mono-ordered g_hist16
    k_scan1  <<< 1, 1024 >>> ((unsigned)n);         // locate cut bins, slots, raw slot LUT
    k_hist2  <<< 888, 512, 65536 >>> (x, n4);       // fine histogram, predicated REDG, 32-bit offsets
    k_scan2  <<< 32, 1024 >>> ();                   // exact order statistics (full-slot block scan)
    k_blutz  <<< BLUTZ_LUT_BLOCKS + BLUTZ_ZERO_BLOCKS, 1024 >>> ();  // params + quant LUT + zero hist2
    k_quant  <<< 1184, 256 >>> (x, out, n4);        // quantize: 2-wide, byte-LUT + conflict-free LDS.128
}

// round 17
// speedup vs baseline: 1.0445x; 1.0034x over previous
#include <cuda_runtime.h>
#include <cstdint>

// ---------------- configuration ----------------
#define HB_BITS   16
#define HB        (1u << HB_BITS)     // 65536 coarse bins (top 16 raw bits)
#define LOWB      16
#define LOWN      (1u << LOWB)        // 65536 fine bins (low 16 mono bits)
#define NPART     148                 // one coarse-hist block per SM
#define MAX_SLOTS 32
#define QL_BITS   14
#define QLN       (1u << QL_BITS)     // 16384-entry quant LUT (top 14 raw bits)

// ---------------- static scratch ----------------
__device__ __align__(16) unsigned g_part1[(size_t)NPART * (HB / 2)];   // 19.4 MB packed u16, overwritten each run
__device__ __align__(16) unsigned g_hist16[HB];                        // mono-indexed, overwritten by k_reduce
__device__ __align__(16) unsigned g_hist2[(size_t)MAX_SLOTS * LOWN];   // 8 MB, zeroed by k_blutz
__device__ __align__(16) unsigned char g_lut16[HB];                    // RAW coarse bin -> slot+1 (rebuilt each run)
__device__ __align__(16) unsigned char g_qlut[QLN];                    // RAW 14-bit bin -> base | amb<<4 (rebuilt)
__device__ int      g_tbin[32];       // mono coarse bins of targets
__device__ unsigned g_trr[32];
__device__ int      g_tslot[32];
__device__ int      g_nslots;
__device__ float    g_tval[32];
__device__ float    g_cutv[16];
__device__ float4   g_q[16];          // x=1/step (A), y=-mn/step (B), z=step (C), w=mn (D)

// order-preserving maps
__device__ __forceinline__ unsigned mono_bits(unsigned b) {
    return b ^ ((unsigned)(((int)b) >> 31) | 0x80000000u);
}
__device__ __forceinline__ unsigned mono_key(float f) { return mono_bits(__float_as_uint(f)); }
__device__ __forceinline__ float unmono_key(unsigned k) {
    unsigned b = (k & 0x80000000u) ? (k & 0x7FFFFFFFu) : ~k;
    return __uint_as_float(b);
}
// 16-bit bin permutations between raw-bit order and mono (value) order
__device__ __forceinline__ unsigned raw2mono16(unsigned r) { return (r & 0x8000u) ? (r ^ 0xFFFFu) : (r ^ 0x8000u); }
__device__ __forceinline__ unsigned mono2raw16(unsigned m) { return (m & 0x8000u) ? (m ^ 0x8000u) : (m ^ 0xFFFFu); }

// ---------------- pass 1: raw 16-bit coarse histogram, packed u16 counters ----------------
__device__ __forceinline__ void h1_acc(unsigned sbase, float4 a) {
    unsigned k0 = __float_as_uint(a.x) >> 16, k1 = __float_as_uint(a.y) >> 16;
    unsigned k2 = __float_as_uint(a.z) >> 16, k3 = __float_as_uint(a.w) >> 16;
    asm volatile("red.shared.add.u32 [%0], %1;" :: "r"(sbase + (k0 >> 1) * 4u), "r"(1u << ((k0 & 1u) << 4)));
    asm volatile("red.shared.add.u32 [%0], %1;" :: "r"(sbase + (k1 >> 1) * 4u), "r"(1u << ((k1 & 1u) << 4)));
    asm volatile("red.shared.add.u32 [%0], %1;" :: "r"(sbase + (k2 >> 1) * 4u), "r"(1u << ((k2 & 1u) << 4)));
    asm volatile("red.shared.add.u32 [%0], %1;" :: "r"(sbase + (k3 >> 1) * 4u), "r"(1u << ((k3 & 1u) << 4)));
}

__global__ void __launch_bounds__(1024) k_hist1(const float4* __restrict__ x, int n4) {
    extern __shared__ unsigned sh[];              // HB/2 = 32768 words (128 KB)
    for (int i = threadIdx.x; i < (int)(HB / 2); i += 1024) sh[i] = 0u;
    __syncthreads();
    unsigned sbase = (unsigned)__cvta_generic_to_shared(sh);
    int T = gridDim.x * blockDim.x;
    int g = blockIdx.x * blockDim.x + threadIdx.x;
    for (int i = g; i < n4; i += 4 * T) {
        float4 a0 = __ldcs(&x[i]);
        bool h1 = (i + T) < n4, h2 = (i + 2 * T) < n4, h3 = (i + 3 * T) < n4;
        float4 a1, a2, a3;
        if (h1) a1 = __ldcs(&x[i + T]);
        if (h2) a2 = __ldcs(&x[i + 2 * T]);
        if (h3) a3 = __ldcs(&x[i + 3 * T]);
        h1_acc(sbase, a0);
        if (h1) h1_acc(sbase, a1);
        if (h2) h1_acc(sbase, a2);
        if (h3) h1_acc(sbase, a3);
    }
    __syncthreads();
    unsigned* dst = g_part1 + (size_t)blockIdx.x * (HB / 2);
    for (int i = threadIdx.x; i < (int)(HB / 2); i += 1024) __stcs(&dst[i], sh[i]);   // packed
}

// ---------------- reduce packed partials -> mono-ordered g_hist16 ----------------
__global__ void __launch_bounds__(1024) k_reduce() {
    unsigned w = blockIdx.x * 1024u + threadIdx.x;     // packed word index (raw bins 2w, 2w+1)
    unsigned lo = 0, hi = 0;
#pragma unroll 8
    for (int k = 0; k < NPART; k++) {
        unsigned v = g_part1[(size_t)k * (HB / 2) + w];
        lo += v & 0xFFFFu;
        hi += v >> 16;
    }
    g_hist16[raw2mono16(2u * w)]      = lo;
    g_hist16[raw2mono16(2u * w + 1u)] = hi;
}

// ---------------- scan coarse histogram (mono order), locate target bins ----------------
__global__ void __launch_bounds__(1024) k_scan1(unsigned n) {
    __shared__ unsigned pre[1024];
    __shared__ unsigned wsum[32];
    __shared__ int      sbin[32];
    __shared__ unsigned srr[32];
    __shared__ int      sslot[32];

    int t = threadIdx.x, lane = t & 31, w = t >> 5;
    unsigned s = 0;
    for (int k = 0; k < 64; k++) s += g_hist16[t * 64 + k];  // group sum (64 mono bins/thread)

    unsigned inc = s;
#pragma unroll
    for (int o = 1; o < 32; o <<= 1) {
        unsigned u = __shfl_up_sync(0xFFFFFFFFu, inc, o);
        if (lane >= o) inc += u;
    }
    if (lane == 31) wsum[w] = inc;
    __syncthreads();
    if (t < 32) {
        unsigned v = wsum[t], ss = v;
#pragma unroll
        for (int o = 1; o < 32; o <<= 1) {
            unsigned u = __shfl_up_sync(0xFFFFFFFFu, ss, o);
            if (t >= o) ss += u;
        }
        wsum[t] = ss - v;
    }
    __syncthreads();
    pre[t] = inc + wsum[w];          // inclusive prefix of 1024 group sums
    __syncthreads();

    if (t < 32) {
        unsigned S = n >> 4;
        unsigned r;
        if (t == 0)       r = 0u;
        else if (t == 31) r = n - 1u;
        else {
            unsigned c = (unsigned)(t + 1) >> 1;
            r = c * S - ((t & 1) ? 1u : 0u);
        }
        int lo = 0, hi = 1023;
        while (lo < hi) { int mid = (lo + hi) >> 1; if (pre[mid] > r) hi = mid; else lo = mid + 1; }
        unsigned run = lo ? pre[lo - 1] : 0u;
        int bin = -1;
        for (int k = 0; k < 64; k++) {
            unsigned c = g_hist16[lo * 64 + k];
            if (r < run + c) { bin = lo * 64 + k; srr[t] = r - run; break; }
            run += c;
        }
        sbin[t] = bin;
    }
    __syncthreads();

    for (int i = t; i < (int)HB; i += 1024) g_lut16[i] = 0;  // zero slot LUT (raw-indexed)
    if (t == 0) {
        int ns = 0;
        for (int i = 0; i < 32; i++) {
            int sl = -1;
            for (int j = 0; j < i; j++) if (sbin[j] == sbin[i]) { sl = sslot[j]; break; }
            if (sl < 0) sl = ns++;
            sslot[i] = sl;
        }
        g_nslots = ns;
    }
    __syncthreads();
    if (t == 0)
        for (int i = 0; i < 32; i++)
            g_lut16[mono2raw16((unsigned)sbin[i])] = (unsigned char)(sslot[i] + 1);
    if (t < 32) { g_tbin[t] = sbin[t]; g_trr[t] = srr[t]; g_tslot[t] = sslot[t]; }
}

// ---------------- pass 2: fine histogram (low 16 mono bits) for cut bins ----------------
// LUT lives in L1 (read-only __ldg; 64 KB, hot). Streaming x uses __ldcs (evict-first)
// so the LUT stays resident. No smem -> 4 blocks/SM resident, single-wave grid.
__device__ __forceinline__ void h2_acc(const unsigned char* __restrict__ lut, float4 a) {
    float vv[4] = { a.x, a.y, a.z, a.w };
#pragma unroll
    for (int j = 0; j < 4; j++) {
        unsigned b = __float_as_uint(vv[j]);
        unsigned sl = __ldg(&lut[b >> 16]);
        unsigned low = (b ^ (unsigned)(((int)b) >> 31)) & 0xFFFFu;
        unsigned off = (((sl - 1u) & 31u) << 16) | low;        // masked: always in-bounds
        unsigned* ptr = g_hist2 + off;
        asm volatile("{\n\t"
                     ".reg .pred p;\n\t"
                     "setp.ne.u32 p, %0, 0;\n\t"
                     "@p red.global.add.u32 [%1], %2;\n\t"
                     "}" :: "r"(sl), "l"(ptr), "r"(1u) : "memory");
    }
}

__global__ void __launch_bounds__(512) k_hist2(const float4* __restrict__ x, int n4) {
    const unsigned char* __restrict__ lut = g_lut16;
    int T = gridDim.x * blockDim.x;
    int g = blockIdx.x * blockDim.x + threadIdx.x;
    for (int i = g; i < n4; i += 4 * T) {
        float4 a0 = __ldcs(&x[i]);
        bool h1 = (i + T) < n4, h2 = (i + 2 * T) < n4, h3 = (i + 3 * T) < n4;
        float4 a1, a2, a3;
        if (h1) a1 = __ldcs(&x[i + T]);
        if (h2) a2 = __ldcs(&x[i + 2 * T]);
        if (h3) a3 = __ldcs(&x[i + 3 * T]);
        h2_acc(lut, a0);
        if (h1) h2_acc(lut, a1);
        if (h2) h2_acc(lut, a2);
        if (h3) h2_acc(lut, a3);
    }
}

// ---------------- scan2: one block per target scans its full 64K-bin slot ----------------
__global__ void __launch_bounds__(1024) k_scan2() {
    int t = blockIdx.x;                    // target 0..31
    int slot = g_tslot[t];
    unsigned rr = g_trr[t];
    unsigned bin = (unsigned)g_tbin[t];
    int tid = threadIdx.x, lane = tid & 31, w = tid >> 5;
    const uint4* h = (const uint4*)(g_hist2 + ((unsigned)slot << 16));

    // pass 1: sum 64 bins (16 uint4) per thread
    unsigned sum = 0;
#pragma unroll
    for (int i = 0; i < 16; i++) {
        uint4 u = h[tid * 16 + i];
        sum += u.x + u.y + u.z + u.w;
    }
    // block inclusive scan of 1024 thread sums
    __shared__ unsigned ws[32];
    unsigned inc = sum;
#pragma unroll
    for (int o = 1; o < 32; o <<= 1) {
        unsigned u = __shfl_up_sync(0xFFFFFFFFu, inc, o);
        if (lane >= o) inc += u;
    }
    if (lane == 31) ws[w] = inc;
    __syncthreads();
    if (tid < 32) {
        unsigned v = ws[tid], ss = v;
#pragma unroll
        for (int o = 1; o < 32; o <<= 1) {
            unsigned u = __shfl_up_sync(0xFFFFFFFFu, ss, o);
            if (tid >= o) ss += u;
        }
        ws[tid] = ss - v;                   // exclusive warp offsets
    }
    __syncthreads();
    unsigned excl = ws[w] + (inc - sum);
    if (rr >= excl && rr < excl + sum) {    // exactly one winner thread
        unsigned run = excl, low = 0;
        bool found = false;
        for (int i = 0; i < 16 && !found; i++) {
            uint4 u = h[tid * 16 + i];      // L1-hot re-read
            unsigned vv[4] = { u.x, u.y, u.z, u.w };
#pragma unroll
            for (int j = 0; j < 4; j++) {
                if (!found) {
                    if (rr < run + vv[j]) { low = (unsigned)(tid * 64 + i * 4 + j); found = true; }
                    else run += vv[j];
                }
            }
        }
        g_tval[t] = unmono_key((bin << LOWB) | low);
    }
}

// ---------------- blutz: per-chunk params + 14-bit quant LUT + zero hist2 ----------------
#define BLUTZ_LUT_BLOCKS (QLN / 1024)      // 16
#define BLUTZ_ZERO_BLOCKS 128
__global__ void __launch_bounds__(1024) k_blutz() {
    if (blockIdx.x < BLUTZ_LUT_BLOCKS) {
        __shared__ unsigned kc[16];
        int t = threadIdx.x;
        if (t < 16) {
            float mn = (t == 0)  ? g_tval[0]  : g_tval[2 * t];
            float mx = (t == 15) ? g_tval[31] : g_tval[2 * t + 1];
            float step = __fdiv_rn(__fsub_rn(mx, mn), 15.0f);
            float inv  = (step == 0.0f) ? 0.0f : __fdiv_rn(1.0f, step);
            float cut  = (t == 0) ? __int_as_float(0xFF800000) : mn;
            kc[t] = mono_key(cut);
            if (blockIdx.x == 0) {          // publish params for k_quant
                g_q[t]    = make_float4(inv, -mn * inv, step, mn);
                g_cutv[t] = cut;
            }
        }
        __syncthreads();
        unsigned r = blockIdx.x * 1024u + t;
        unsigned m0 = mono_bits(r << (32 - QL_BITS));
        unsigned m1 = mono_bits((r << (32 - QL_BITS)) | ((1u << (32 - QL_BITS)) - 1u));
        unsigned mlo = min(m0, m1), mhi = max(m0, m1);
        int base = 0, amb = 0;
#pragma unroll
        for (int j = 1; j < 16; j++) {
            unsigned k = kc[j];
            base += (k <= mlo);
            amb  += (k > mlo && k <= mhi);
        }
        g_qlut[r] = (unsigned char)(base | (amb << 4));
    } else {
        // zero the used fine-histogram slots for the next graph replay
        unsigned total4 = (unsigned)g_nslots * (LOWN / 4u);
        uint4* p = (uint4*)g_hist2;
        uint4 z = make_uint4(0u, 0u, 0u, 0u);
        unsigned id = (blockIdx.x - BLUTZ_LUT_BLOCKS) * 1024u + threadIdx.x;
        unsigned stride = BLUTZ_ZERO_BLOCKS * 1024u;
        for (; id < total4; id += stride) p[id] = z;
    }
}

// ---------------- final quantize pass (R14-proven 2-wide) ----------------
// Params via conflict-free replicated LDS.128: pq[c*8 + (lane&7)].
__device__ __forceinline__ float qone(float v, const unsigned char* lut,
                                      const float4* pq, const float* scut, int rep) {
    unsigned e = lut[__float_as_uint(v) >> (32 - QL_BITS)];
    int b = e & 15;
    int amb = e >> 4;
    int c = b + (int)((amb > 0) & (v >= scut[b + 1]));   // unconditional single fix-up
    if (amb > 1) {                                        // essentially never taken
#pragma unroll 1
        for (int t2 = 2; t2 <= amb; t2++) c += (v >= scut[b + t2]) ? 1 : 0;
    }
    float4 p = pq[c * 8 + rep];                           // {A, B, C, D}
    return fmaf(rintf(fmaf(v, p.x, p.y)), p.z, p.w);      // A==0 -> result D == mn == v
}

__global__ void __launch_bounds__(256) k_quant(const float4* __restrict__ x,
                                               float4* __restrict__ o, int n4) {
    __shared__ unsigned char lut[QLN];           // 16 KB
    __shared__ float4 pq[16 * 8];                // 2 KB replicated params
    __shared__ float  scut[20];
    {
        const uint4* src = (const uint4*)g_qlut;
        uint4* dst = (uint4*)lut;
        for (int i = threadIdx.x; i < (int)(QLN / 16); i += 256) dst[i] = src[i];
    }
    if (threadIdx.x < 128) pq[threadIdx.x] = g_q[threadIdx.x >> 3];
    if (threadIdx.x < 16)  scut[threadIdx.x] = g_cutv[threadIdx.x];
    if (threadIdx.x >= 16 && threadIdx.x < 20) scut[threadIdx.x] = __int_as_float(0x7F800000); // +inf pad
    __syncthreads();
    int rep = threadIdx.x & 7;
    int T = gridDim.x * blockDim.x;
    int g = blockIdx.x * blockDim.x + threadIdx.x;
    for (int i = g; i < n4; i += 2 * T) {        // warp-uniform bounds (n4, T multiples of 32)
        float4 a = __ldcs(&x[i]);
        bool hb = (i + T) < n4;
        float4 b;
        if (hb) b = __ldcs(&x[i + T]);
        float4 ra;
        ra.x = qone(a.x, lut, pq, scut, rep);
        ra.y = qone(a.y, lut, pq, scut, rep);
        ra.z = qone(a.z, lut, pq, scut, rep);
        ra.w = qone(a.w, lut, pq, scut, rep);
        __stcs(&o[i], ra);
        if (hb) {
            float4 rb;
            rb.x = qone(b.x, lut, pq, scut, rep);
            rb.y = qone(b.y, lut, pq, scut, rep);
            rb.z = qone(b.z, lut, pq, scut, rep);
            rb.w = qone(b.w, lut, pq, scut, rep);
            __stcs(&o[i + T], rb);
        }
    }
}

// ---------------- launcher ----------------
extern "C" void kernel_launch(void* const* d_in, const int* in_sizes, int n_in,
                              void* d_out, int out_size) {
    const float4* x = (const float4*)d_in[0];
    float4* out = (float4*)d_out;
    int n = in_sizes[0];
    int n4 = n / 4;

    cudaFuncSetAttribute(k_hist1, cudaFuncAttributeMaxDynamicSharedMemorySize, 131072);

    k_hist1  <<< NPART, 1024, 131072 >>> (x, n4);   // raw 16-bit coarse histogram (packed u16)
    k_reduce <<< (HB / 2) / 1024, 1024 >>> ();      // sum packed partials -> mono-ordered g_hist16
    k_scan1  <<< 1, 1024 >>> ((unsigned)n);         // locate cut bins, slots, raw slot LUT
    k_hist2  <<< 592, 512 >>> (x, n4);              // fine histogram: L1 LUT, 4/SM single wave
    k_scan2  <<< 32, 1024 >>> ();                   // exact order statistics (full-slot block scan)
    k_blutz  <<< BLUTZ_LUT_BLOCKS + BLUTZ_ZERO_BLOCKS, 1024 >>> ();  // params + quant LUT + zero hist2
    k_quant  <<< 1184, 256 >>> (x, out, n4);        // quantize: 2-wide, byte-LUT + conflict-free LDS.128
}